// round 17
// baseline (speedup 1.0000x reference)
#include <cuda_runtime.h>
#include <cuda_bf16.h>
#include <math.h>
#include <stdint.h>

#define BATCH 4
#define SEQ   4096
#define NROWS (BATCH * SEQ)
#define EMB   768
#define QD    64
#define CCOLS 192
#define NCTAS 128

// ---------------- scratch ----------------------------------------------------
__device__ float g_C[(size_t)NROWS * CCOLS];
__device__ __nv_bfloat16 g_Bh[(size_t)EMB * CCOLS];  // k-major: [k][n]
__device__ __nv_bfloat16 g_Bl[(size_t)EMB * CCOLS];
__device__ float g_Spart[128 * 64];                  // per-CTA V col sums
__device__ unsigned g_barCnt = 0;                    // monotonic, replay-safe

// ---------------- PTX helpers ------------------------------------------------
__device__ __forceinline__ uint32_t smem_u32(const void* p) {
    uint32_t a;
    asm("{ .reg .u64 t; cvta.to.shared.u64 t, %1; cvt.u32.u64 %0, t; }"
        : "=r"(a) : "l"(p));
    return a;
}
#define LDM4(r, addr)                                                        \
    asm volatile("ldmatrix.sync.aligned.m8n8.x4.shared.b16 {%0,%1,%2,%3}, [%4];" \
                 : "=r"((r)[0]), "=r"((r)[1]), "=r"((r)[2]), "=r"((r)[3])    \
                 : "r"(addr))
#define LDMT4(r, addr)                                                       \
    asm volatile("ldmatrix.sync.aligned.m8n8.x4.trans.shared.b16 {%0,%1,%2,%3}, [%4];" \
                 : "=r"((r)[0]), "=r"((r)[1]), "=r"((r)[2]), "=r"((r)[3])    \
                 : "r"(addr))
#define MMA(d, a, b0, b1)                                                    \
    asm volatile(                                                            \
        "mma.sync.aligned.m16n8k16.row.col.f32.bf16.bf16.f32 "               \
        "{%0,%1,%2,%3}, {%4,%5,%6,%7}, {%8,%9}, {%0,%1,%2,%3};"              \
        : "+f"((d)[0]), "+f"((d)[1]), "+f"((d)[2]), "+f"((d)[3])             \
        : "r"((a)[0]), "r"((a)[1]), "r"((a)[2]), "r"((a)[3]),                \
          "r"(b0), "r"(b1))
#define CP16(dst, src)                                                       \
    asm volatile("cp.async.cg.shared.global [%0], [%1], 16;"                 \
                 :: "r"(dst), "l"(src))
#define CP_COMMIT() asm volatile("cp.async.commit_group;")
#define CP_WAIT1()  asm volatile("cp.async.wait_group 1;")
#define CP_WAIT0()  asm volatile("cp.async.wait_group 0;")

// Grid-wide barrier. Safe: all 128 CTAs resident (1 CTA/SM via 176KB smem,
// 128 < 148 SMs -> single wave). Monotonic counter, no reset, replay-safe.
__device__ __forceinline__ void grid_barrier() {
    __syncthreads();
    if (threadIdx.x == 0) {
        __threadfence();
        unsigned my = atomicAdd(&g_barCnt, 1u);
        unsigned target = (my & ~(unsigned)(NCTAS - 1)) + NCTAS;
        while ((int)(*(volatile unsigned*)&g_barCnt - target) < 0)
            __nanosleep(64);
        __threadfence();
    }
    __syncthreads();
}

// ---------------- single fused kernel -----------------------------------------
#define SA_BYTES (128 * 144)
#define SB_BYTES (64 * 400)
#define SA_OFF(s, h) (((s) * 2 + (h)) * SA_BYTES)
#define SB_OFF(s, h) (4 * SA_BYTES + ((s) * 2 + (h)) * SB_BYTES)
#define SM_TOTAL (4 * SA_BYTES + 4 * SB_BYTES)   // 176128

__global__ __launch_bounds__(256, 1)
void fused_all(const float* __restrict__ x,
               const float* __restrict__ Wq, const float* __restrict__ bq,
               const float* __restrict__ Wk, const float* __restrict__ bk,
               const float* __restrict__ Wv, const float* __restrict__ bv,
               float* __restrict__ out)
{
    extern __shared__ char smem[];
    __shared__ float sbias[CCOLS];
    __shared__ float smemV[4][64];
    __shared__ float sS[64];

    const uint32_t sb = smem_u32(smem);
    const int tid = threadIdx.x;
    const int wid = tid >> 5, lane = tid & 31;
    const int wm = wid & 3, wn = wid >> 2;
    const int rowTile = blockIdx.x * 128;
    const int batch = blockIdx.x >> 5;

    // ---- phase 0: weight split, my 1/128 slice ----
    {
        const int base = blockIdx.x * (EMB * CCOLS / 2 / NCTAS);
        for (int t = tid; t < EMB * CCOLS / 2 / NCTAS; t += 256) {
            int q = base + t;
            int n2 = (q % (CCOLS / 2)) * 2;
            int k  = q / (CCOLS / 2);
            const float* W = (n2 < 64) ? Wq : (n2 < 128) ? Wk : Wv;
            float2 v = *(const float2*)(W + (size_t)k * 64 + (n2 & 63));
            __nv_bfloat162 h01 = __floats2bfloat162_rn(v.x, v.y);
            float l0 = v.x - __bfloat162float(h01.x);
            float l1 = v.y - __bfloat162float(h01.y);
            __nv_bfloat162 p01 = __floats2bfloat162_rn(l0, l1);
            size_t o = (size_t)k * CCOLS + n2;
            *(uint32_t*)(g_Bh + o) = *(uint32_t*)&h01;
            *(uint32_t*)(g_Bl + o) = *(uint32_t*)&p01;
        }
    }
    if (tid < CCOLS)
        sbias[tid] = (tid < 64) ? bq[tid] : (tid < 128) ? bk[tid - 64]
                                                        : bv[tid - 128];
    grid_barrier();

    // ---- phase 1: GEMM (byte-identical to R13) ----
    float acc[2][12][4];
#pragma unroll
    for (int i = 0; i < 2; i++)
#pragma unroll
        for (int j = 0; j < 12; j++)
#pragma unroll
            for (int l = 0; l < 4; l++) acc[i][j][l] = 0.f;

    const int g = lane >> 3, r = lane & 7;
    const int a_off = (r + ((g & 1) ? 8 : 0)) * 144 + (((g >= 2) ? 8 : 0) * 2);
    const int b_off = ((g & 1) * 8 + r) * 400 + (((g >= 2) ? 8 : 0) * 2);

    uint32_t aAh[2], aAl[2], aBh[2], aBl[2];
#pragma unroll
    for (int s = 0; s < 2; s++) {
        aAh[s] = sb + SA_OFF(s, 0) + wm * 32 * 144 + a_off;
        aAl[s] = sb + SA_OFF(s, 1) + wm * 32 * 144 + a_off;
        aBh[s] = sb + SB_OFF(s, 0) + wn * 96 * 2 + b_off;
        aBl[s] = sb + SB_OFF(s, 1) + wn * 96 * 2 + b_off;
    }

    float4 Av[8];

#define LDG_A_RAW(ch)                                                        \
    do {                                                                     \
        const int k0_ = (ch) * 64;                                           \
        _Pragma("unroll")                                                    \
        for (int i = 0; i < 8; i++) {                                        \
            int idx = tid + i * 256;                                         \
            int rr = idx >> 4, c4 = idx & 15;                                \
            Av[i] = *(const float4*)(x + (size_t)(rowTile + rr) * EMB +      \
                                     k0_ + c4 * 4);                          \
        }                                                                    \
    } while (0)

#define STS_A_CONV(ch)                                                       \
    do {                                                                     \
        const int s_ = (ch) & 1;                                             \
        _Pragma("unroll")                                                    \
        for (int i = 0; i < 8; i++) {                                        \
            int idx = tid + i * 256;                                         \
            int rr = idx >> 4, c4 = idx & 15;                                \
            float4 v = Av[i];                                                \
            __nv_bfloat162 h01 = __floats2bfloat162_rn(v.x, v.y);            \
            __nv_bfloat162 h23 = __floats2bfloat162_rn(v.z, v.w);            \
            float l0 = v.x - __bfloat162float(h01.x);                        \
            float l1 = v.y - __bfloat162float(h01.y);                        \
            float l2 = v.z - __bfloat162float(h23.x);                        \
            float l3 = v.w - __bfloat162float(h23.y);                        \
            __nv_bfloat162 p01 = __floats2bfloat162_rn(l0, l1);              \
            __nv_bfloat162 p23 = __floats2bfloat162_rn(l2, l3);              \
            *(uint2*)(smem + SA_OFF(s_, 0) + rr * 144 + c4 * 8) =            \
                make_uint2(*(uint32_t*)&h01, *(uint32_t*)&h23);              \
            *(uint2*)(smem + SA_OFF(s_, 1) + rr * 144 + c4 * 8) =            \
                make_uint2(*(uint32_t*)&p01, *(uint32_t*)&p23);              \
        }                                                                    \
    } while (0)

#define LDG_B(ch)                                                            \
    do {                                                                     \
        const int s_ = (ch) & 1;                                             \
        const int k0_ = (ch) * 64;                                           \
        _Pragma("unroll")                                                    \
        for (int i = 0; i < 6; i++) {                                        \
            int j = tid + i * 256;                                           \
            int row = j / 24, c = j % 24;                                    \
            uint32_t dh = sb + SB_OFF(s_, 0) + row * 400 + c * 16;           \
            uint32_t dl = sb + SB_OFF(s_, 1) + row * 400 + c * 16;           \
            CP16(dh, g_Bh + (size_t)(k0_ + row) * CCOLS + c * 8);            \
            CP16(dl, g_Bl + (size_t)(k0_ + row) * CCOLS + c * 8);            \
        }                                                                    \
    } while (0)

    // ---- prologue ----
    LDG_B(0); CP_COMMIT();
    LDG_A_RAW(0);
    STS_A_CONV(0);
    LDG_B(1); CP_COMMIT();
    LDG_A_RAW(1);

    // ---- main loop ----
    for (int ch = 0; ch < 12; ch++) {
        const int s = ch & 1;
        if (ch < 11) CP_WAIT1(); else CP_WAIT0();
        __syncthreads();

#pragma unroll
        for (int ks = 0; ks < 4; ks++) {
            uint32_t ah[2][4], al[2][4];
            LDM4(ah[0], aAh[s] + ks * 32);
            LDM4(ah[1], aAh[s] + 16 * 144 + ks * 32);
            LDM4(al[0], aAl[s] + ks * 32);
            LDM4(al[1], aAl[s] + 16 * 144 + ks * 32);

            uint32_t bh[2][4], bl[2][4];
            LDMT4(bh[0], aBh[s] + ks * 6400);
            LDMT4(bl[0], aBl[s] + ks * 6400);
#pragma unroll
            for (int nt = 0; nt < 6; nt++) {
                const int cur = nt & 1, nxt = cur ^ 1;
                if (nt < 5) {
                    LDMT4(bh[nxt], aBh[s] + ks * 6400 + (nt + 1) * 32);
                    LDMT4(bl[nxt], aBl[s] + ks * 6400 + (nt + 1) * 32);
                }
#pragma unroll
                for (int mt = 0; mt < 2; mt++) {
                    MMA(acc[mt][2 * nt],     ah[mt], bh[cur][0], bh[cur][1]);
                    MMA(acc[mt][2 * nt],     ah[mt], bl[cur][0], bl[cur][1]);
                    MMA(acc[mt][2 * nt],     al[mt], bh[cur][0], bh[cur][1]);
                    MMA(acc[mt][2 * nt + 1], ah[mt], bh[cur][2], bh[cur][3]);
                    MMA(acc[mt][2 * nt + 1], ah[mt], bl[cur][2], bl[cur][3]);
                    MMA(acc[mt][2 * nt + 1], al[mt], bh[cur][2], bh[cur][3]);
                }
            }
            if (ks == 0 && ch < 11)
                STS_A_CONV(ch + 1);   // A[s^1] only — safe
        }
        if (ch < 10) {
            __syncthreads();          // all reads of B[s] complete
            LDG_B(ch + 2); CP_COMMIT();
            LDG_A_RAW(ch + 2);
        }
    }

    // ---- write g_C (+bias) ----
    const int rbase = rowTile + wm * 32 + (lane >> 2);
#pragma unroll
    for (int mt = 0; mt < 2; mt++)
#pragma unroll
        for (int nt = 0; nt < 12; nt++) {
            int col = wn * 96 + nt * 8 + 2 * (lane & 3);
            float b0 = sbias[col], b1 = sbias[col + 1];
            int row = rbase + mt * 16;
            *(float2*)&g_C[(size_t)row * CCOLS + col] =
                make_float2(acc[mt][nt][0] + b0, acc[mt][nt][1] + b1);
            *(float2*)&g_C[(size_t)(row + 8) * CCOLS + col] =
                make_float2(acc[mt][nt][2] + b0, acc[mt][nt][3] + b1);
        }

    // ---- per-CTA V column sums ----
    if (wn == 1) {
#pragma unroll
        for (int nt = 4; nt < 12; nt++) {
            float s0 = acc[0][nt][0] + acc[0][nt][2] + acc[1][nt][0] + acc[1][nt][2];
            float s1 = acc[0][nt][1] + acc[0][nt][3] + acc[1][nt][1] + acc[1][nt][3];
#pragma unroll
            for (int m = 4; m <= 16; m <<= 1) {
                s0 += __shfl_xor_sync(0xffffffffu, s0, m);
                s1 += __shfl_xor_sync(0xffffffffu, s1, m);
            }
            if (lane < 4) {
                int d = (nt - 4) * 8 + 2 * lane;
                smemV[wm][d] = s0;
                smemV[wm][d + 1] = s1;
            }
        }
    }
    __syncthreads();
    if (tid < 64)
        g_Spart[blockIdx.x * 64 + tid] =
            smemV[0][tid] + smemV[1][tid] + smemV[2][tid] + smemV[3][tid] +
            128.f * sbias[128 + tid];

    grid_barrier();

    // ---- phase 2: per-batch S (replicated per CTA, deterministic) ----
    if (tid < 64) {
        float s = 0.f;
#pragma unroll
        for (int c = 0; c < 32; c++)
            s += g_Spart[(batch * 32 + c) * 64 + tid];
#pragma unroll
        for (int j = 0; j < 3; j++)
            s -= g_C[(size_t)(batch * SEQ + j) * CCOLS + 128 + tid];
        sS[tid] = s;
    }
    __syncthreads();

    // ---- phase 3: attention epilogue, 8 row-pairs per warp (L2-hot) ----
    {
        const float* Vb = g_C + (size_t)(batch * SEQ) * CCOLS + 128;
        float2 v0 = *(const float2*)(Vb + lane * 2);
        float2 v1 = *(const float2*)(Vb + CCOLS + lane * 2);
        float2 v2 = *(const float2*)(Vb + 2 * CCOLS + lane * 2);
        float2 sv = *(const float2*)(sS + lane * 2);

        for (int pr = 0; pr < 8; pr++) {
            const int r0 = rowTile + wid * 16 + pr * 2;   // even
            const int r1 = r0 + 1;
            const int loc0 = r0 & (SEQ - 1);
            const int loc1 = r1 & (SEQ - 1);

            const float* C0 = g_C + (size_t)r0 * CCOLS;
            float2 q0 = *(const float2*)(C0 + lane * 2);
            float2 q1 = *(const float2*)(C0 + CCOLS + lane * 2);

            const float* K0 = C0 + 64;
            float2 k0  = *(const float2*)(K0 + lane * 2);
            float2 k1  = *(const float2*)(K0 + CCOLS + lane * 2);
            float2 km1 = make_float2(0.f, 0.f), k2 = make_float2(0.f, 0.f);
            if (loc0 > 0)
                km1 = *(const float2*)(K0 - CCOLS + lane * 2);
            if (loc1 < SEQ - 1)
                k2 = *(const float2*)(K0 + 2 * CCOLS + lane * 2);

            float dA = q0.x * km1.x + q0.y * km1.y;
            float dB = q0.x * k0.x + q0.y * k0.y;
            float dC = q0.x * k1.x + q0.y * k1.y;
            float dD = q1.x * k0.x + q1.y * k0.y;
            float dE = q1.x * k1.x + q1.y * k1.y;
            float dF = q1.x * k2.x + q1.y * k2.y;
#pragma unroll
            for (int off = 16; off; off >>= 1) {
                dA += __shfl_xor_sync(0xffffffffu, dA, off);
                dB += __shfl_xor_sync(0xffffffffu, dB, off);
                dC += __shfl_xor_sync(0xffffffffu, dC, off);
                dD += __shfl_xor_sync(0xffffffffu, dD, off);
                dE += __shfl_xor_sync(0xffffffffu, dE, off);
                dF += __shfl_xor_sync(0xffffffffu, dF, off);
            }
            float e0_0 = (loc0 > 0) ? __expf(dA) : 1.f;
            float e1_0 = __expf(dB);
            float e2_0 = __expf(dC);
            float e0_1 = __expf(dD);
            float e1_1 = __expf(dE);
            float e2_1 = (loc1 < SEQ - 1) ? __expf(dF) : 1.f;
            float rZ0 = __fdividef(1.f, e0_0 + e1_0 + e2_0 + (float)(SEQ - 3));
            float rZ1 = __fdividef(1.f, e0_1 + e1_1 + e2_1 + (float)(SEQ - 3));

            float2 o0, o1;
            o0.x = (e0_0 * v0.x + e1_0 * v1.x + e2_0 * v2.x + sv.x) * rZ0;
            o0.y = (e0_0 * v0.y + e1_0 * v1.y + e2_0 * v2.y + sv.y) * rZ0;
            o1.x = (e0_1 * v0.x + e1_1 * v1.x + e2_1 * v2.x + sv.x) * rZ1;
            o1.y = (e0_1 * v0.y + e1_1 * v1.y + e2_1 * v2.y + sv.y) * rZ1;
            *(float2*)(out + (size_t)r0 * QD + lane * 2) = o0;
            *(float2*)(out + (size_t)r1 * QD + lane * 2) = o1;
        }
    }
}

// ---------------- launch -------------------------------------------------------
extern "C" void kernel_launch(void* const* d_in, const int* in_sizes, int n_in,
                              void* d_out, int out_size)
{
    const float* x  = (const float*)d_in[0];
    const float* Wq = (const float*)d_in[1];
    const float* bq = (const float*)d_in[2];
    const float* Wk = (const float*)d_in[3];
    const float* bk = (const float*)d_in[4];
    const float* Wv = (const float*)d_in[5];
    const float* bv = (const float*)d_in[6];
    float* out = (float*)d_out;

    cudaFuncSetAttribute(fused_all, cudaFuncAttributeMaxDynamicSharedMemorySize,
                         SM_TOTAL);
    fused_all<<<NCTAS, 256, SM_TOTAL>>>(x, Wq, bq, Wk, bk, Wv, bv, out);
}